// round 7
// baseline (speedup 1.0000x reference)
#include <cuda_runtime.h>
#include <cstdint>

#define S_DIM 384

__device__ float g_A[12288 * 512];   // [m = i*32+c][k=n]  (1/512 folded, tf32-rounded)
__device__ float g_B[12288 * 512];   // [p = j*32+d][k=n]  (tf32-rounded)
__device__ float g_W2[1024 * 128];   // [k' = d*32+c][zz]  (transposed+permuted, tf32-rounded)

// ---------------------------------------------------------------- helpers
__device__ __forceinline__ uint32_t smem_u32(const void* p) {
    uint32_t a;
    asm("{ .reg .u64 t; cvta.to.shared.u64 t, %1; cvt.u32.u64 %0, t; }" : "=r"(a) : "l"(p));
    return a;
}
__device__ __forceinline__ float tf32rn(float x) {
    uint32_t r; asm("cvt.rna.tf32.f32 %0, %1;" : "=r"(r) : "f"(x));
    return __uint_as_float(r);
}
__device__ __forceinline__ uint32_t lds32(uint32_t a) {
    uint32_t v; asm volatile("ld.shared.b32 %0, [%1];" : "=r"(v) : "r"(a)); return v;
}
__device__ __forceinline__ void sts32(uint32_t a, float v) {
    asm volatile("st.shared.b32 [%0], %1;" :: "r"(a), "f"(v) : "memory");
}
__device__ __forceinline__ void cp16(uint32_t dst, const float* src) {
    asm volatile("cp.async.cg.shared.global [%0], [%1], 16;" :: "r"(dst), "l"(src));
}
#define CP_COMMIT() asm volatile("cp.async.commit_group;" ::: "memory")
#define CP_WAIT1()  asm volatile("cp.async.wait_group 1;" ::: "memory")
#define CP_WAIT0()  asm volatile("cp.async.wait_group 0;" ::: "memory")

// m16n8k8 tf32 MMA (base ISA, sm_80+): D += A*B
__device__ __forceinline__ void mma8(float* d, const uint32_t* a, uint32_t b0, uint32_t b1) {
    asm volatile(
        "mma.sync.aligned.m16n8k8.row.col.f32.tf32.tf32.f32 "
        "{%0,%1,%2,%3}, {%4,%5,%6,%7}, {%8,%9}, {%0,%1,%2,%3};"
        : "+f"(d[0]), "+f"(d[1]), "+f"(d[2]), "+f"(d[3])
        : "r"(a[0]), "r"(a[1]), "r"(a[2]), "r"(a[3]), "r"(b0), "r"(b1));
}

// ---------------------------------------------------------------- kernel 1: LN + proj (+ W prep)
__global__ __launch_bounds__(256) void ln_proj_kernel(
    const float* __restrict__ m_si, const float* __restrict__ ln_g,
    const float* __restrict__ ln_b, const float* __restrict__ w_ab,
    const float* __restrict__ w_final)
{
    extern __shared__ char smem_raw[];
    float* sm  = reinterpret_cast<float*>(smem_raw);
    float* ws  = sm;            // [64][33]
    float* a_s = sm + 2112;     // [32][513]
    float* b_s = sm + 18528;    // [32][513]

    int t = threadIdx.x, warp = t >> 5, lane = t & 31;
    int s = blockIdx.x;

    // fold W prep into first 256 blocks: g_W2[k'][zz] = tf32(w[zz][c*32+d]), k'=d*32+c
    if (s < 256) {
        #pragma unroll
        for (int q = 0; q < 2; q++) {
            int idx = q * 256 + t;
            int kk = s * 4 + (idx >> 7);     // k' row
            int zz = idx & 127;
            int d = kk >> 5, c = kk & 31;
            g_W2[kk * 128 + zz] = tf32rn(w_final[zz * 1024 + c * 32 + d]);
        }
    }

    for (int idx = t; idx < 64 * 32; idx += 256)
        ws[(idx >> 5) * 33 + (idx & 31)] = w_ab[idx];
    __syncthreads();

    float g = ln_g[lane], bb = ln_b[lane];

    for (int it = 0; it < 64; it++) {
        int n = warp * 64 + it;
        float x = m_si[((size_t)(s * 512 + n)) * 32 + lane];

        float sum = x;
        #pragma unroll
        for (int o = 16; o; o >>= 1) sum += __shfl_xor_sync(0xFFFFFFFFu, sum, o);
        float mu = sum * (1.0f / 32.0f);
        float dx = x - mu;
        float v = dx * dx;
        #pragma unroll
        for (int o = 16; o; o >>= 1) v += __shfl_xor_sync(0xFFFFFFFFu, v, o);
        float mn = dx * rsqrtf(v * (1.0f / 32.0f) + 1e-5f) * g + bb;

        float aa = 0.0f, ab = 0.0f;
        #pragma unroll
        for (int c = 0; c < 32; c++) {
            float mc = __shfl_sync(0xFFFFFFFFu, mn, c);
            aa += mc * ws[lane * 33 + c];
            ab += mc * ws[(lane + 32) * 33 + c];
        }
        a_s[lane * 513 + n] = aa * (1.0f / 512.0f);
        b_s[lane * 513 + n] = ab;
    }
    __syncthreads();

    for (int q = 0; q < 64; q++) {
        int idx = q * 256 + t;
        int c = idx >> 9, n = idx & 511;
        g_A[((size_t)(s * 32 + c)) * 512 + n] = tf32rn(a_s[c * 513 + n]);
        g_B[((size_t)(s * 32 + c)) * 512 + n] = tf32rn(b_s[c * 513 + n]);
    }
}

// ---------------------------------------------------------------- kernel 2: fused tensor GEMMs
// SMEM (bytes): mainloop 3 stages x (A 16K + B 32K) = 147456 at offset 0.
// epilogue reuse: osm [1024 k'][40 floats] = 163840 at 0; per-warp W stage:
//   163840 + w*3072 (+1536 for buf1), 16 k'-rows x 24 words (96B) each.
#define STG_B   49152u
#define OFF_WS  163840u
#define SMEM2   212992

__device__ __forceinline__ void load_AB(uint32_t sb, int ch, int slot,
                                        int m0, int p0, int t) {
    int k0 = ch * 32;
    uint32_t sA = sb + (uint32_t)slot * STG_B;
    uint32_t sB = sA + 16384u;
    #pragma unroll
    for (int q = 0; q < 2; q++) {
        int idx = t + q * 512, row = idx >> 3, c = idx & 7;
        cp16(sA + row * 128u + ((uint32_t)(c ^ (row & 7)) << 4),
             g_A + (size_t)(m0 + row) * 512 + k0 + c * 4);
    }
    #pragma unroll
    for (int q = 0; q < 4; q++) {
        int idx = t + q * 512, row = idx >> 3, c = idx & 7;
        cp16(sB + row * 128u + ((uint32_t)(c ^ (row & 7)) << 4),
             g_B + (size_t)(p0 + row) * 512 + k0 + c * 4);
    }
}

__device__ __forceinline__ void load_Wc(uint32_t sb, int ch, int buf,
                                        int w, int lane) {
    uint32_t wsb = sb + OFF_WS + (uint32_t)w * 3072u + (buf ? 1536u : 0u);
    int zg = w >> 1;
    #pragma unroll
    for (int q = 0; q < 2; q++) {
        int idx = lane + q * 32, kk = idx >> 2, seg = idx & 3;
        cp16(wsb + kk * 96u + seg * 16u,
             g_W2 + (size_t)(ch * 16 + kk) * 128 + zg * 16 + seg * 4);
    }
}

__global__ __launch_bounds__(512) void opm_mma_kernel(
    const float* __restrict__ b_final, float* __restrict__ z)
{
    extern __shared__ char smem_raw[];
    uint32_t sb = smem_u32(smem_raw);

    int t = threadIdx.x, w = t >> 5, lane = t & 31;
    int g = lane >> 2, r = lane & 3;
    int wm = w >> 3, wn = w & 7;                 // warp grid 2(m) x 8(p)
    int m0 = blockIdx.y * 128, p0 = blockIdx.x * 256;
    uint32_t r4 = (uint32_t)r * 4u;

    float acc[4][4][4];
    #pragma unroll
    for (int i = 0; i < 4; i++)
        #pragma unroll
        for (int j = 0; j < 4; j++)
            #pragma unroll
            for (int cc = 0; cc < 4; cc++) acc[i][j][cc] = 0.0f;

    // ---- mainloop: o = A * B^T (K=512, 16 chunks of 32, 3-stage pipeline)
    load_AB(sb, 0, 0, m0, p0, t); CP_COMMIT();
    load_AB(sb, 1, 1, m0, p0, t); CP_COMMIT();

    for (int s = 0; s < 16; s++) {
        if (s < 15) CP_WAIT1(); else CP_WAIT0();
        __syncthreads();

        uint32_t sA = sb + (uint32_t)(s % 3) * STG_B;
        uint32_t sB = sA + 16384u;

        #pragma unroll
        for (int ks = 0; ks < 4; ks++) {
            uint32_t off0 = (((uint32_t)((2 * ks) ^ g)) << 4) + r4;
            uint32_t off1 = (((uint32_t)((2 * ks + 1) ^ g)) << 4) + r4;

            uint32_t a[4][4];
            #pragma unroll
            for (int i = 0; i < 4; i++) {
                uint32_t rowb = sA + (uint32_t)(wm * 64 + i * 16 + g) * 128u;
                a[i][0] = lds32(rowb + off0);
                a[i][1] = lds32(rowb + 1024u + off0);   // row +8
                a[i][2] = lds32(rowb + off1);
                a[i][3] = lds32(rowb + 1024u + off1);
            }
            #pragma unroll
            for (int j = 0; j < 4; j++) {
                uint32_t prow = sB + (uint32_t)(wn * 32 + j * 8 + g) * 128u;
                uint32_t b0 = lds32(prow + off0);
                uint32_t b1 = lds32(prow + off1);
                #pragma unroll
                for (int i = 0; i < 4; i++) mma8(acc[i][j], a[i], b0, b1);
            }
        }

        if (s + 2 < 16) { load_AB(sb, s + 2, (s + 2) % 3, m0, p0, t); CP_COMMIT(); }
    }
    __syncthreads();                 // all warps done with mainloop smem

    // ---- prefetch W chunks 0,1 (per-warp) while spilling o
    load_Wc(sb, 0, 0, w, lane); CP_COMMIT();
    load_Wc(sb, 1, 1, w, lane); CP_COMMIT();

    // ---- spill o to osm[k'=d*32+c][pair] (stride 40 floats), tf32-rounded
    #pragma unroll
    for (int i = 0; i < 4; i++)
        #pragma unroll
        for (int j = 0; j < 4; j++)
            #pragma unroll
            for (int cc = 0; cc < 4; cc++) {
                int m = wm * 64 + i * 16 + g + ((cc & 2) ? 8 : 0);
                int p = wn * 32 + j * 8 + 2 * r + (cc & 1);
                int kp   = (p & 31) * 32 + (m & 31);
                int pair = ((m >> 5) << 3) | (p >> 5);
                sts32(sb + (uint32_t)((kp * 40 + pair) * 4), tf32rn(acc[i][j][cc]));
            }
    __syncthreads();

    // ---- epilogue GEMM: z[zz][pair] = W' * o'  (M=128, N=32, K=1024)
    // per-warp: zz rows zg*16..+15, pair tiles {jbase, jbase+1}; 64 chunks of k'=16,
    // per-warp double-buffered W staging, NO block syncs.
    int zg = w >> 1, jbase = (w & 1) * 2;
    float zacc[2][4];
    #pragma unroll
    for (int jj = 0; jj < 2; jj++)
        #pragma unroll
        for (int cc = 0; cc < 4; cc++) zacc[jj][cc] = 0.0f;

    for (int ch = 0; ch < 64; ch++) {
        int buf = ch & 1;
        if (ch < 63) CP_WAIT1(); else CP_WAIT0();
        __syncwarp();

        uint32_t wsb = sb + OFF_WS + (uint32_t)w * 3072u + (buf ? 1536u : 0u);
        #pragma unroll
        for (int ks = 0; ks < 2; ks++) {
            int kb = ks * 8;
            uint32_t ar = wsb + (uint32_t)(kb + r) * 96u + (uint32_t)g * 4u;
            uint32_t aw[4];
            aw[0] = lds32(ar);           // (zz = zg16+g,   k)
            aw[1] = lds32(ar + 32u);     // (zz+8,          k)
            aw[2] = lds32(ar + 384u);    // (zz,            k+4)
            aw[3] = lds32(ar + 416u);    // (zz+8,          k+4)

            #pragma unroll
            for (int jj = 0; jj < 2; jj++) {
                uint32_t brow = sb + (uint32_t)(((ch * 16 + kb + r) * 40
                                 + (jbase + jj) * 8 + g) * 4);
                uint32_t b0 = lds32(brow);
                uint32_t b1 = lds32(brow + 640u);     // k+4 -> +4*40 words
                mma8(zacc[jj], aw, b0, b1);
            }
        }
        if (ch + 2 < 64) { load_Wc(sb, ch + 2, buf, w, lane); CP_COMMIT(); }
    }

    // ---- write z (+bias)
    float bf0 = b_final[zg * 16 + g];
    float bf1 = b_final[zg * 16 + g + 8];
    #pragma unroll
    for (int jj = 0; jj < 2; jj++)
        #pragma unroll
        for (int cc = 0; cc < 4; cc++) {
            int zz = zg * 16 + g + ((cc & 2) ? 8 : 0);
            int n  = (jbase + jj) * 8 + 2 * r + (cc & 1);   // pair 0..31
            int ig = blockIdx.y * 4 + (n >> 3);
            int jg = blockIdx.x * 8 + (n & 7);
            z[((size_t)(ig * S_DIM + jg)) * 128 + zz] =
                zacc[jj][cc] + ((cc & 2) ? bf1 : bf0);
        }
}

// ---------------------------------------------------------------- launch
extern "C" void kernel_launch(void* const* d_in, const int* in_sizes, int n_in,
                              void* d_out, int out_size)
{
    const float* m_si    = (const float*)d_in[0];
    const float* ln_g    = (const float*)d_in[1];
    const float* ln_b    = (const float*)d_in[2];
    const float* w_ab    = (const float*)d_in[3];
    const float* w_final = (const float*)d_in[4];
    const float* b_final = (const float*)d_in[5];
    float* z = (float*)d_out;
    (void)in_sizes; (void)n_in; (void)out_size;

    cudaFuncSetAttribute(ln_proj_kernel,
                         cudaFuncAttributeMaxDynamicSharedMemorySize, 139776);
    ln_proj_kernel<<<S_DIM, 256, 139776>>>(m_si, ln_g, ln_b, w_ab, w_final);

    cudaFuncSetAttribute(opm_mma_kernel,
                         cudaFuncAttributeMaxDynamicSharedMemorySize, SMEM2);
    dim3 grid(48, 96);   // (p-tiles, m-tiles)
    opm_mma_kernel<<<grid, 512, SMEM2>>>(b_final, z);
}

// round 8
// speedup vs baseline: 1.1879x; 1.1879x over previous
#include <cuda_runtime.h>
#include <cstdint>

#define S_DIM 384

// Fragment-layout operand buffers (permutations written by kernel 1):
// g_A: [MI=m/16 (768)][kf=k/8 (64)][512B frag: lane*16 + word*4]
//      word = (mrow>>3) + 2*((k>>2)&1), lane = (m&7)*4 + (k&3)
// g_B: [NI=p/8 (1536)][kf (64)][256B frag: lane*8 + word*4], word=(k>>2)&1
// g_W2:[zg=zz/16 (8)][kf'=k'/8 (128)][512B frag]  (k' = d*32 + c)
__device__ float g_A[12288 * 512];
__device__ float g_B[12288 * 512];
__device__ float g_W2[128 * 1024];

// ---------------------------------------------------------------- helpers
__device__ __forceinline__ uint32_t smem_u32(const void* p) {
    uint32_t a;
    asm("{ .reg .u64 t; cvta.to.shared.u64 t, %1; cvt.u32.u64 %0, t; }" : "=r"(a) : "l"(p));
    return a;
}
__device__ __forceinline__ float tf32rn(float x) {
    uint32_t r; asm("cvt.rna.tf32.f32 %0, %1;" : "=r"(r) : "f"(x));
    return __uint_as_float(r);
}
__device__ __forceinline__ void lds128(uint32_t* v, uint32_t a) {
    asm volatile("ld.shared.v4.b32 {%0,%1,%2,%3}, [%4];"
                 : "=r"(v[0]), "=r"(v[1]), "=r"(v[2]), "=r"(v[3]) : "r"(a));
}
__device__ __forceinline__ void lds64(uint32_t* v, uint32_t a) {
    asm volatile("ld.shared.v2.b32 {%0,%1}, [%2];"
                 : "=r"(v[0]), "=r"(v[1]) : "r"(a));
}
__device__ __forceinline__ void sts32(uint32_t a, float v) {
    asm volatile("st.shared.b32 [%0], %1;" :: "r"(a), "f"(v) : "memory");
}
__device__ __forceinline__ void cp16(uint32_t dst, const float* src) {
    asm volatile("cp.async.cg.shared.global [%0], [%1], 16;" :: "r"(dst), "l"(src));
}
#define CP_COMMIT() asm volatile("cp.async.commit_group;" ::: "memory")
#define CP_WAIT2()  asm volatile("cp.async.wait_group 2;" ::: "memory")
#define CP_WAIT1()  asm volatile("cp.async.wait_group 1;" ::: "memory")
#define CP_WAIT0()  asm volatile("cp.async.wait_group 0;" ::: "memory")

// m16n8k8 tf32 MMA: D += A*B
__device__ __forceinline__ void mma8(float* d, const uint32_t* a, uint32_t b0, uint32_t b1) {
    asm volatile(
        "mma.sync.aligned.m16n8k8.row.col.f32.tf32.tf32.f32 "
        "{%0,%1,%2,%3}, {%4,%5,%6,%7}, {%8,%9}, {%0,%1,%2,%3};"
        : "+f"(d[0]), "+f"(d[1]), "+f"(d[2]), "+f"(d[3])
        : "r"(a[0]), "r"(a[1]), "r"(a[2]), "r"(a[3]), "r"(b0), "r"(b1));
}

// ---------------------------------------------------------------- kernel 1: LN + proj + W prep
__global__ __launch_bounds__(256) void ln_proj_kernel(
    const float* __restrict__ m_si, const float* __restrict__ ln_g,
    const float* __restrict__ ln_b, const float* __restrict__ w_ab,
    const float* __restrict__ w_final)
{
    extern __shared__ char smem_raw[];
    float* sm  = reinterpret_cast<float*>(smem_raw);
    float* ws  = sm;            // [64][33]
    float* a_s = sm + 2112;     // [32][513]
    float* b_s = sm + 18528;    // [32][513]

    int t = threadIdx.x, warp = t >> 5, lane = t & 31;
    int s = blockIdx.x;

    // W prep (first 256 blocks): g_W2 fragment layout, k' = d*32 + c
    if (s < 256) {
        #pragma unroll
        for (int q = 0; q < 2; q++) {
            int idx = q * 256 + t;
            int kk = s * 4 + (idx >> 7);    // k' row 0..1023
            int zz = idx & 127;
            float v = tf32rn(w_final[zz * 1024 + (kk & 31) * 32 + (kk >> 5)]);
            int zg = zz >> 4;
            int off = zg * 16384 + (kk >> 3) * 128
                    + ((zz & 7) * 4 + (kk & 3)) * 4
                    + ((zz >> 3) & 1) + ((kk >> 2) & 1) * 2;
            g_W2[off] = v;
        }
    }

    for (int idx = t; idx < 64 * 32; idx += 256)
        ws[(idx >> 5) * 33 + (idx & 31)] = w_ab[idx];
    __syncthreads();

    float g = ln_g[lane], bb = ln_b[lane];

    for (int it = 0; it < 64; it++) {
        int n = warp * 64 + it;
        float x = m_si[((size_t)(s * 512 + n)) * 32 + lane];

        float sum = x;
        #pragma unroll
        for (int o = 16; o; o >>= 1) sum += __shfl_xor_sync(0xFFFFFFFFu, sum, o);
        float mu = sum * (1.0f / 32.0f);
        float dx = x - mu;
        float v = dx * dx;
        #pragma unroll
        for (int o = 16; o; o >>= 1) v += __shfl_xor_sync(0xFFFFFFFFu, v, o);
        float mn = dx * rsqrtf(v * (1.0f / 32.0f) + 1e-5f) * g + bb;

        float aa = 0.0f, ab = 0.0f;
        #pragma unroll
        for (int c = 0; c < 32; c++) {
            float mc = __shfl_sync(0xFFFFFFFFu, mn, c);
            aa += mc * ws[lane * 33 + c];
            ab += mc * ws[(lane + 32) * 33 + c];
        }
        a_s[lane * 513 + n] = aa * (1.0f / 512.0f);
        b_s[lane * 513 + n] = ab;
    }
    __syncthreads();

    // write out in fragment layout, tf32-rounded
    for (int q = 0; q < 64; q++) {
        int idx = q * 256 + t;
        int c = idx >> 9, n = idx & 511;       // m = s*32 + c, k = n
        float va = tf32rn(a_s[c * 513 + n]);
        float vb = tf32rn(b_s[c * 513 + n]);

        int MI = s * 2 + (c >> 4);
        int offA = MI * 8192 + (n >> 3) * 128
                 + ((c & 7) * 4 + (n & 3)) * 4
                 + ((c >> 3) & 1) + ((n >> 2) & 1) * 2;
        g_A[offA] = va;

        int NI = s * 4 + (c >> 3);
        int offB = NI * 4096 + (n >> 3) * 64
                 + ((c & 7) * 4 + (n & 3)) * 2 + ((n >> 2) & 1);
        g_B[offB] = vb;
    }
}

// ---------------------------------------------------------------- kernel 2
// SMEM: 4 stages x 48KB (A 16K + B 32K) = 196608.
// epilogue reuse: osm frag layout [kf' 128][pf 4][256B] = 131072 at 0;
// per-warp W stage at 131072 + w*2048 + buf*1024 (1KB = 2 frags / chunk).
#define STG     49152u
#define OFF_WS  131072u
#define SMEM2   196608

__device__ __forceinline__ void load_AB(uint32_t slot, int ch, int mi0, int ni0, int t) {
    // A: 1024 16B units: [MI 8][ksf 4][32 units]
    #pragma unroll
    for (int q = 0; q < 2; q++) {
        int idx = t + q * 512;
        int MIi = idx >> 7, ksf = (idx >> 5) & 3, unit = idx & 31;
        cp16(slot + (uint32_t)idx * 16u,
             g_A + (size_t)(mi0 + MIi) * 8192 + (ch * 4 + ksf) * 128 + unit * 4);
    }
    // B: 2048 units: [NI 32][ksf 4][16 units]
    #pragma unroll
    for (int q = 0; q < 4; q++) {
        int idx = t + q * 512;
        int NIl = idx >> 6, ksf = (idx >> 4) & 3, unit = idx & 15;
        cp16(slot + 16384u + (uint32_t)idx * 16u,
             g_B + (size_t)(ni0 + NIl) * 4096 + (ch * 4 + ksf) * 64 + unit * 4);
    }
}

__device__ __forceinline__ void load_Wc(uint32_t sb, int ch, int buf, int w, int lane) {
    uint32_t wsb = sb + OFF_WS + (uint32_t)w * 2048u + (buf ? 1024u : 0u);
    int zg = w >> 1;
    #pragma unroll
    for (int q = 0; q < 2; q++) {
        int idx = lane + q * 32;
        int kfl = idx >> 5, unit = idx & 31;
        cp16(wsb + (uint32_t)idx * 16u,
             g_W2 + (size_t)zg * 16384 + (ch * 2 + kfl) * 128 + unit * 4);
    }
}

__global__ __launch_bounds__(512) void opm_mma_kernel(
    const float* __restrict__ b_final, float* __restrict__ z)
{
    extern __shared__ char smem_raw[];
    uint32_t sb = smem_u32(smem_raw);

    int t = threadIdx.x, w = t >> 5, lane = t & 31;
    int g = lane >> 2, r = lane & 3;
    int wm = w >> 3, wn = w & 7;                  // 2(m) x 8(p) warps, 64x32 tiles
    int mi0 = blockIdx.y * 8;                     // MI base (m0/16)
    int ni0 = blockIdx.x * 32;                    // NI base (p0/8)
    uint32_t l16 = (uint32_t)lane * 16u, l8 = (uint32_t)lane * 8u;

    float acc[4][4][4];
    #pragma unroll
    for (int i = 0; i < 4; i++)
        #pragma unroll
        for (int j = 0; j < 4; j++)
            #pragma unroll
            for (int cc = 0; cc < 4; cc++) acc[i][j][cc] = 0.0f;

    // ---- mainloop: 16 chunks of k=32, 4-stage pipeline
    load_AB(sb + 0u * STG, 0, mi0, ni0, t); CP_COMMIT();
    load_AB(sb + 1u * STG, 1, mi0, ni0, t); CP_COMMIT();
    load_AB(sb + 2u * STG, 2, mi0, ni0, t); CP_COMMIT();

    for (int s = 0; s < 16; s++) {
        if (s < 14) CP_WAIT2(); else if (s == 14) CP_WAIT1(); else CP_WAIT0();
        __syncthreads();

        uint32_t slot = sb + (uint32_t)(s & 3) * STG;
        uint32_t aBase = slot + (uint32_t)(wm * 16) * 512u;          // (wm*4+i)*4+ks
        uint32_t bBase = slot + 16384u + (uint32_t)(wn * 16) * 256u; // (wn*4+j)*4+ks

        #pragma unroll
        for (int ks = 0; ks < 4; ks++) {
            uint32_t a[4][4], b[4][2];
            #pragma unroll
            for (int i = 0; i < 4; i++)
                lds128(a[i], aBase + (uint32_t)(i * 4 + ks) * 512u + l16);
            #pragma unroll
            for (int j = 0; j < 4; j++)
                lds64(b[j], bBase + (uint32_t)(j * 4 + ks) * 256u + l8);
            #pragma unroll
            for (int i = 0; i < 4; i++)
                #pragma unroll
                for (int j = 0; j < 4; j++)
                    mma8(acc[i][j], a[i], b[j][0], b[j][1]);
        }

        if (s + 3 < 16) {
            load_AB(sb + (uint32_t)((s + 3) & 3) * STG, s + 3, mi0, ni0, t);
            CP_COMMIT();
        }
    }
    __syncthreads();

    // ---- prefetch W chunks 0,1 (per-warp), then spill o (frag layout, tf32)
    load_Wc(sb, 0, 0, w, lane); CP_COMMIT();
    load_Wc(sb, 1, 1, w, lane); CP_COMMIT();

    #pragma unroll
    for (int i = 0; i < 4; i++)
        #pragma unroll
        for (int j = 0; j < 4; j++)
            #pragma unroll
            for (int cc = 0; cc < 4; cc++) {
                int m = wm * 64 + i * 16 + g + ((cc & 2) ? 8 : 0);
                int p = wn * 32 + j * 8 + 2 * r + (cc & 1);
                int kp   = (p & 31) * 32 + (m & 31);          // k'
                int pair = ((m >> 5) << 3) | (p >> 5);
                int off = ((kp >> 3) * 4 + (pair >> 3)) * 256
                        + ((pair & 7) * 4 + (kp & 3)) * 8 + ((kp >> 2) & 1) * 4;
                sts32(sb + (uint32_t)off, tf32rn(acc[i][j][cc]));
            }
    __syncthreads();

    // ---- epilogue: z[zz][pair] = W' * o' (K=1024, 64 chunks of 16)
    int zg = w >> 1, pfb = (w & 1) * 2;
    float zacc[2][4];
    #pragma unroll
    for (int jj = 0; jj < 2; jj++)
        #pragma unroll
        for (int cc = 0; cc < 4; cc++) zacc[jj][cc] = 0.0f;

    for (int ch = 0; ch < 64; ch++) {
        int buf = ch & 1;
        if (ch < 63) CP_WAIT1(); else CP_WAIT0();
        __syncwarp();

        uint32_t wsb = sb + OFF_WS + (uint32_t)w * 2048u + (buf ? 1024u : 0u);
        #pragma unroll
        for (int ks = 0; ks < 2; ks++) {
            uint32_t aw[4];
            lds128(aw, wsb + (uint32_t)ks * 512u + l16);
            #pragma unroll
            for (int jj = 0; jj < 2; jj++) {
                uint32_t b[2];
                lds64(b, sb + (uint32_t)(((ch * 2 + ks) * 4 + pfb + jj) * 256) + l8);
                mma8(zacc[jj], aw, b[0], b[1]);
            }
        }
        if (ch + 2 < 64) { load_Wc(sb, ch + 2, buf, w, lane); CP_COMMIT(); }
    }

    // ---- write z (+bias)
    float bf0 = b_final[zg * 16 + g];
    float bf1 = b_final[zg * 16 + g + 8];
    #pragma unroll
    for (int jj = 0; jj < 2; jj++)
        #pragma unroll
        for (int cc = 0; cc < 4; cc++) {
            int zz = zg * 16 + g + ((cc & 2) ? 8 : 0);
            int n  = (pfb + jj) * 8 + 2 * r + (cc & 1);     // pair 0..31
            int ig = blockIdx.y * 4 + (n >> 3);
            int jg = blockIdx.x * 8 + (n & 7);
            z[((size_t)(ig * S_DIM + jg)) * 128 + zz] =
                zacc[jj][cc] + ((cc & 2) ? bf1 : bf0);
        }
}

// ---------------------------------------------------------------- launch
extern "C" void kernel_launch(void* const* d_in, const int* in_sizes, int n_in,
                              void* d_out, int out_size)
{
    const float* m_si    = (const float*)d_in[0];
    const float* ln_g    = (const float*)d_in[1];
    const float* ln_b    = (const float*)d_in[2];
    const float* w_ab    = (const float*)d_in[3];
    const float* w_final = (const float*)d_in[4];
    const float* b_final = (const float*)d_in[5];
    float* z = (float*)d_out;
    (void)in_sizes; (void)n_in; (void)out_size;

    cudaFuncSetAttribute(ln_proj_kernel,
                         cudaFuncAttributeMaxDynamicSharedMemorySize, 139776);
    ln_proj_kernel<<<S_DIM, 256, 139776>>>(m_si, ln_g, ln_b, w_ab, w_final);

    cudaFuncSetAttribute(opm_mma_kernel,
                         cudaFuncAttributeMaxDynamicSharedMemorySize, SMEM2);
    dim3 grid(48, 96);   // (p-tiles, m-tiles)
    opm_mma_kernel<<<grid, 512, SMEM2>>>(b_final, z);
}

// round 9
// speedup vs baseline: 1.3905x; 1.1706x over previous
#include <cuda_runtime.h>
#include <cstdint>

#define S_DIM 384

// Fragment-layout operand buffers (permutations written by kernel 1):
// g_A: [MI=m/16 (768)][kf=k/8 (64)][512B frag]
// g_B: [NI=p/8 (1536)][kf (64)][256B frag]
// g_W2:[zg=zz/16 (8)][kf'=k'/8 (128)][512B frag]  (k' = d*32 + c)
__device__ float g_A[12288 * 512];
__device__ float g_B[12288 * 512];
__device__ float g_W2[128 * 1024];

// ---------------------------------------------------------------- helpers
__device__ __forceinline__ uint32_t smem_u32(const void* p) {
    uint32_t a;
    asm("{ .reg .u64 t; cvta.to.shared.u64 t, %1; cvt.u32.u64 %0, t; }" : "=r"(a) : "l"(p));
    return a;
}
__device__ __forceinline__ float tf32rn(float x) {
    uint32_t r; asm("cvt.rna.tf32.f32 %0, %1;" : "=r"(r) : "f"(x));
    return __uint_as_float(r);
}
__device__ __forceinline__ void lds128(uint32_t* v, uint32_t a) {
    asm volatile("ld.shared.v4.b32 {%0,%1,%2,%3}, [%4];"
                 : "=r"(v[0]), "=r"(v[1]), "=r"(v[2]), "=r"(v[3]) : "r"(a));
}
__device__ __forceinline__ void lds64(uint32_t* v, uint32_t a) {
    asm volatile("ld.shared.v2.b32 {%0,%1}, [%2];"
                 : "=r"(v[0]), "=r"(v[1]) : "r"(a));
}
__device__ __forceinline__ void sts32(uint32_t a, float v) {
    asm volatile("st.shared.b32 [%0], %1;" :: "r"(a), "f"(v) : "memory");
}
__device__ __forceinline__ void cp16(uint32_t dst, const float* src) {
    asm volatile("cp.async.cg.shared.global [%0], [%1], 16;" :: "r"(dst), "l"(src));
}
#define CP_COMMIT() asm volatile("cp.async.commit_group;" ::: "memory")
#define CP_WAIT1()  asm volatile("cp.async.wait_group 1;" ::: "memory")
#define CP_WAIT0()  asm volatile("cp.async.wait_group 0;" ::: "memory")

// m16n8k8 tf32 MMA: D += A*B
__device__ __forceinline__ void mma8(float* d, const uint32_t* a, uint32_t b0, uint32_t b1) {
    asm volatile(
        "mma.sync.aligned.m16n8k8.row.col.f32.tf32.tf32.f32 "
        "{%0,%1,%2,%3}, {%4,%5,%6,%7}, {%8,%9}, {%0,%1,%2,%3};"
        : "+f"(d[0]), "+f"(d[1]), "+f"(d[2]), "+f"(d[3])
        : "r"(a[0]), "r"(a[1]), "r"(a[2]), "r"(a[3]), "r"(b0), "r"(b1));
}

// ---------------------------------------------------------------- kernel 1: LN + proj + W prep
// 1536 blocks: b -> (s = b>>2, n-slice of 128). W prep spread over blocks 0..511.
__global__ __launch_bounds__(256) void ln_proj_kernel(
    const float* __restrict__ m_si, const float* __restrict__ ln_g,
    const float* __restrict__ ln_b, const float* __restrict__ w_ab,
    const float* __restrict__ w_final)
{
    __shared__ float ws[64 * 33];
    __shared__ float a_s[32 * 129];
    __shared__ float b_s[32 * 129];

    int t = threadIdx.x, warp = t >> 5, lane = t & 31;
    int b = blockIdx.x;
    int s = b >> 2, n0 = (b & 3) * 128;

    if (b < 512) {   // W prep: g_W2 fragment layout, k' = d*32+c
        int i  = b * 256 + t;          // 0..131071
        int kk = i >> 7, zz = i & 127;
        float v = tf32rn(w_final[zz * 1024 + (kk & 31) * 32 + (kk >> 5)]);
        int off = (zz >> 4) * 16384 + (kk >> 3) * 128
                + ((zz & 7) * 4 + (kk & 3)) * 4
                + ((zz >> 3) & 1) + ((kk >> 2) & 1) * 2;
        g_W2[off] = v;
    }

    for (int idx = t; idx < 64 * 32; idx += 256)
        ws[(idx >> 5) * 33 + (idx & 31)] = w_ab[idx];
    __syncthreads();

    float g = ln_g[lane], bb = ln_b[lane];

    for (int it = 0; it < 16; it++) {
        int nl = warp * 16 + it;                 // 0..127
        float x = m_si[((size_t)(s * 512 + n0 + nl)) * 32 + lane];

        float sum = x;
        #pragma unroll
        for (int o = 16; o; o >>= 1) sum += __shfl_xor_sync(0xFFFFFFFFu, sum, o);
        float mu = sum * (1.0f / 32.0f);
        float dx = x - mu;
        float v = dx * dx;
        #pragma unroll
        for (int o = 16; o; o >>= 1) v += __shfl_xor_sync(0xFFFFFFFFu, v, o);
        float mn = dx * rsqrtf(v * (1.0f / 32.0f) + 1e-5f) * g + bb;

        float aa = 0.0f, ab = 0.0f;
        #pragma unroll
        for (int c = 0; c < 32; c++) {
            float mc = __shfl_sync(0xFFFFFFFFu, mn, c);
            aa += mc * ws[lane * 33 + c];
            ab += mc * ws[(lane + 32) * 33 + c];
        }
        a_s[lane * 129 + nl] = aa * (1.0f / 512.0f);
        b_s[lane * 129 + nl] = ab;
    }
    __syncthreads();

    #pragma unroll
    for (int q = 0; q < 16; q++) {
        int idx = q * 256 + t;
        int c = idx >> 7, nl = idx & 127;        // m = s*32+c, k = n0+nl
        int n = n0 + nl;
        float va = tf32rn(a_s[c * 129 + nl]);
        float vb = tf32rn(b_s[c * 129 + nl]);

        int MI = s * 2 + (c >> 4);
        g_A[MI * 8192 + (n >> 3) * 128
            + ((c & 7) * 4 + (n & 3)) * 4
            + ((c >> 3) & 1) + ((n >> 2) & 1) * 2] = va;

        int NI = s * 4 + (c >> 3);
        g_B[NI * 4096 + (n >> 3) * 64
            + ((c & 7) * 4 + (n & 3)) * 2 + ((n >> 2) & 1)] = vb;
    }
}

// ---------------------------------------------------------------- kernel 2
// 256 threads, tile 128(m) x 128(p). SMEM: 3 stages x 32KB (A 16K + B 16K).
// Epilogue reuse: osm frag layout [kf' 128][pf 2][256B] = 64KB at 0;
// per-warp W stage at 65536 + w*2048 + buf*1024.
#define STG     32768u
#define OFF_WS  65536u
#define SMEM2   98304

__device__ __forceinline__ void load_AB(uint32_t slot, int ch, int mi0, int ni0, int t) {
    #pragma unroll
    for (int q = 0; q < 4; q++) {                 // A: 1024 16B units
        int idx = t + q * 256;
        int MIi = idx >> 7, ksf = (idx >> 5) & 3, unit = idx & 31;
        cp16(slot + (uint32_t)idx * 16u,
             g_A + (size_t)(mi0 + MIi) * 8192 + (ch * 4 + ksf) * 128 + unit * 4);
    }
    #pragma unroll
    for (int q = 0; q < 4; q++) {                 // B: 1024 units
        int idx = t + q * 256;
        int NIl = idx >> 6, ksf = (idx >> 4) & 3, unit = idx & 15;
        cp16(slot + 16384u + (uint32_t)idx * 16u,
             g_B + (size_t)(ni0 + NIl) * 4096 + (ch * 4 + ksf) * 64 + unit * 4);
    }
}

__device__ __forceinline__ void load_Wc(uint32_t sb, int ch, int buf, int w, int lane) {
    uint32_t wsb = sb + OFF_WS + (uint32_t)w * 2048u + (buf ? 1024u : 0u);
    #pragma unroll
    for (int q = 0; q < 2; q++) {
        int idx = lane + q * 32;
        int kfl = idx >> 5, unit = idx & 31;
        cp16(wsb + (uint32_t)idx * 16u,
             g_W2 + (size_t)w * 16384 + (ch * 2 + kfl) * 128 + unit * 4);
    }
}

__global__ __launch_bounds__(256, 2) void opm_mma_kernel(
    const float* __restrict__ b_final, float* __restrict__ z)
{
    extern __shared__ char smem_raw[];
    uint32_t sb = smem_u32(smem_raw);

    int t = threadIdx.x, w = t >> 5, lane = t & 31;
    int g = lane >> 2, r = lane & 3;
    int wm = w >> 2, wn = w & 3;                 // 2(m) x 4(p) warps, 64x32 tiles
    int mi0 = blockIdx.y * 8;                    // MI base
    int ni0 = blockIdx.x * 16;                   // NI base
    uint32_t l16 = (uint32_t)lane * 16u, l8 = (uint32_t)lane * 8u;

    float acc[4][4][4];
    #pragma unroll
    for (int i = 0; i < 4; i++)
        #pragma unroll
        for (int j = 0; j < 4; j++)
            #pragma unroll
            for (int cc = 0; cc < 4; cc++) acc[i][j][cc] = 0.0f;

    // ---- mainloop: 16 chunks of k=32, 3-stage pipeline
    load_AB(sb + 0u * STG, 0, mi0, ni0, t); CP_COMMIT();
    load_AB(sb + 1u * STG, 1, mi0, ni0, t); CP_COMMIT();

    for (int s = 0; s < 16; s++) {
        if (s < 15) CP_WAIT1(); else CP_WAIT0();
        __syncthreads();

        uint32_t slot = sb + (uint32_t)(s % 3) * STG;
        uint32_t aBase = slot + (uint32_t)(wm * 16) * 512u;
        uint32_t bBase = slot + 16384u + (uint32_t)(wn * 16) * 256u;

        #pragma unroll
        for (int ks = 0; ks < 4; ks++) {
            uint32_t a[4][4], b[4][2];
            #pragma unroll
            for (int i = 0; i < 4; i++)
                lds128(a[i], aBase + (uint32_t)(i * 4 + ks) * 512u + l16);
            #pragma unroll
            for (int j = 0; j < 4; j++)
                lds64(b[j], bBase + (uint32_t)(j * 4 + ks) * 256u + l8);
            #pragma unroll
            for (int i = 0; i < 4; i++)
                #pragma unroll
                for (int j = 0; j < 4; j++)
                    mma8(acc[i][j], a[i], b[j][0], b[j][1]);
        }

        if (s + 2 < 16) {
            load_AB(sb + (uint32_t)((s + 2) % 3) * STG, s + 2, mi0, ni0, t);
            CP_COMMIT();
        }
    }
    __syncthreads();

    // ---- prefetch W chunks 0,1 (per-warp), then spill o (frag layout, tf32)
    load_Wc(sb, 0, 0, w, lane); CP_COMMIT();
    load_Wc(sb, 1, 1, w, lane); CP_COMMIT();

    #pragma unroll
    for (int i = 0; i < 4; i++)
        #pragma unroll
        for (int j = 0; j < 4; j++)
            #pragma unroll
            for (int cc = 0; cc < 4; cc++) {
                int m = wm * 64 + i * 16 + g + ((cc & 2) ? 8 : 0);
                int p = wn * 32 + j * 8 + 2 * r + (cc & 1);
                int kp   = (p & 31) * 32 + (m & 31);             // k'
                int pair = ((m >> 5) << 2) | (p >> 5);           // 0..15
                int off = ((kp >> 3) * 2 + (pair >> 3)) * 256
                        + ((pair & 7) * 4 + (kp & 3)) * 8 + ((kp >> 2) & 1) * 4;
                sts32(sb + (uint32_t)off, tf32rn(acc[i][j][cc]));
            }
    __syncthreads();

    // ---- epilogue: z[zz][pair] = W' * o' (K=1024, 64 chunks of 16)
    // warp w owns zz rows w*16..+15 and BOTH pair tiles (pf = 0,1).
    float zacc[2][4];
    #pragma unroll
    for (int jj = 0; jj < 2; jj++)
        #pragma unroll
        for (int cc = 0; cc < 4; cc++) zacc[jj][cc] = 0.0f;

    for (int ch = 0; ch < 64; ch++) {
        int buf = ch & 1;
        if (ch < 63) CP_WAIT1(); else CP_WAIT0();
        __syncwarp();

        uint32_t wsb = sb + OFF_WS + (uint32_t)w * 2048u + (buf ? 1024u : 0u);
        #pragma unroll
        for (int ks = 0; ks < 2; ks++) {
            uint32_t aw[4];
            lds128(aw, wsb + (uint32_t)ks * 512u + l16);
            #pragma unroll
            for (int jj = 0; jj < 2; jj++) {
                uint32_t b[2];
                lds64(b, sb + (uint32_t)(((ch * 2 + ks) * 2 + jj) * 256) + l8);
                mma8(zacc[jj], aw, b[0], b[1]);
            }
        }
        if (ch + 2 < 64) { load_Wc(sb, ch + 2, buf, w, lane); CP_COMMIT(); }
    }

    // ---- write z (+bias)
    float bf0 = b_final[w * 16 + g];
    float bf1 = b_final[w * 16 + g + 8];
    #pragma unroll
    for (int jj = 0; jj < 2; jj++)
        #pragma unroll
        for (int cc = 0; cc < 4; cc++) {
            int zz = w * 16 + g + ((cc & 2) ? 8 : 0);
            int pr = jj * 8 + 2 * r + (cc & 1);              // pair 0..15
            int ig = blockIdx.y * 4 + (pr >> 2);
            int jg = blockIdx.x * 4 + (pr & 3);
            z[((size_t)(ig * S_DIM + jg)) * 128 + zz] =
                zacc[jj][cc] + ((cc & 2) ? bf1 : bf0);
        }
}

// ---------------------------------------------------------------- launch
extern "C" void kernel_launch(void* const* d_in, const int* in_sizes, int n_in,
                              void* d_out, int out_size)
{
    const float* m_si    = (const float*)d_in[0];
    const float* ln_g    = (const float*)d_in[1];
    const float* ln_b    = (const float*)d_in[2];
    const float* w_ab    = (const float*)d_in[3];
    const float* w_final = (const float*)d_in[4];
    const float* b_final = (const float*)d_in[5];
    float* z = (float*)d_out;
    (void)in_sizes; (void)n_in; (void)out_size;

    ln_proj_kernel<<<1536, 256>>>(m_si, ln_g, ln_b, w_ab, w_final);

    cudaFuncSetAttribute(opm_mma_kernel,
                         cudaFuncAttributeMaxDynamicSharedMemorySize, SMEM2);
    dim3 grid(96, 96);   // (p-tiles, m-tiles), 128x128 each
    opm_mma_kernel<<<grid, 256, SMEM2>>>(b_final, z);
}